// round 5
// baseline (speedup 1.0000x reference)
#include <cuda_runtime.h>
#include <cuda_fp16.h>
#include <cstdint>

// DAS beamforming, fp16-staged smem gather, 4-deep cp.async pipeline,
// fine-grained CTAs (4 channels per block) to avoid wave quantization.
// Pass 1: convert rf (fp32, 8MB, L2-resident) -> fp16 __device__ buffer (4MB).
// Pass 2: per block (batch, 2048-pixel tile, 4-channel group): pipeline each
// channel's fp16 row (16KB) through a 4-buffer smem ring via cp.async (one
// __syncthreads per channel), gather y0/y1 as 8B LDS, lerp in fp32, combine
// group partials with red.global.add.v4.f32.

namespace {
constexpr int NB = 2;
constexpr int NC = 128;
constexpr int NS = 2048;
constexpr int M  = 65536;                 // Nz*Nx per batch
constexpr int THREADS = 512;
constexpr int PXT = 4;                    // pixels per thread
constexpr int TILE_P = THREADS * PXT;     // 2048
constexpr int TILES = M / TILE_P;         // 32
constexpr int CPG = 4;                    // channels per group (per block)
constexpr int NG  = NC / CPG;             // 32
constexpr int ROW_BYTES = NS * 8;         // fp16 row: 2048 samples * 8B
constexpr int NBUF = 4;
constexpr int SMEM_BYTES = NBUF * ROW_BYTES;   // 64KB ring
constexpr int NSAMP = NB * NC * NS;       // 524288 samples
}

__device__ uint2 g_rf16[NSAMP];           // [B][Nc][Ns] x 4 halves = 4MB

__device__ __forceinline__ void cp_async16(uint32_t smem_addr, const void* gptr) {
    asm volatile("cp.async.cg.shared.global [%0], [%1], 16;\n"
                 :: "r"(smem_addr), "l"(gptr) : "memory");
}
__device__ __forceinline__ void cp_async_commit() {
    asm volatile("cp.async.commit_group;\n" ::: "memory");
}
template <int N>
__device__ __forceinline__ void cp_async_wait() {
    asm volatile("cp.async.wait_group %0;\n" :: "n"(N) : "memory");
}
__device__ __forceinline__ void red_add_v4(float* ptr, float4 v) {
    asm volatile("red.global.add.v4.f32 [%0], {%1, %2, %3, %4};\n"
                 :: "l"(ptr), "f"(v.x), "f"(v.y), "f"(v.z), "f"(v.w)
                 : "memory");
}

__global__ __launch_bounds__(256)
void rf_to_fp16_kernel(const float4* __restrict__ rf) {
    const int i = blockIdx.x * blockDim.x + threadIdx.x;
    if (i < NSAMP) {
        const float4 v = rf[i];
        const __half2 h0 = __float22half2_rn(make_float2(v.x, v.y));
        const __half2 h1 = __float22half2_rn(make_float2(v.z, v.w));
        uint2 u;
        u.x = *reinterpret_cast<const unsigned int*>(&h0);
        u.y = *reinterpret_cast<const unsigned int*>(&h1);
        g_rf16[i] = u;
    }
}

__global__ __launch_bounds__(THREADS, 3)
void das_fp16_kernel(const float* __restrict__ g,
                     const float* __restrict__ pr,
                     const float* __restrict__ p,
                     float* __restrict__ out) {
    extern __shared__ uint2 sbuf[];                 // [NBUF][NS] samples
    __shared__ float sprx[CPG], spry[CPG], sprz[CPG];

    const int tid  = threadIdx.x;
    int idx = blockIdx.x;
    const int b    = idx / (TILES * NG);
    idx -= b * (TILES * NG);
    const int tile = idx / NG;
    const int grp  = idx - tile * NG;
    const int c0   = grp * CPG;
    const int pm   = tile * TILE_P;

    if (tid < CPG) {
        const float* prb = pr + ((size_t)b * NC + (c0 + tid)) * 3;
        sprx[tid] = prb[0];
        spry[tid] = prb[1];
        sprz[tid] = prb[2];
    }

    const float c0s = p[b * 4 + 0];
    const float fs  = p[b * 4 + 1];
    const float t0  = p[b * 4 + 2];
    const float scale = fs / c0s;
    const float tbase = fs * t0 / c0s;

    float gx[PXT], gy[PXT], gz[PXT];
    float4 acc[PXT];
    #pragma unroll
    for (int j = 0; j < PXT; ++j) {
        const int m = pm + tid + j * THREADS;
        const float* gp = g + ((size_t)b * M + m) * 3;
        gx[j] = gp[0];
        gy[j] = gp[1];
        gz[j] = gp[2];
        acc[j] = make_float4(0.f, 0.f, 0.f, 0.f);
    }

    const uint2* rfb = g_rf16 + (size_t)b * NC * NS;
    const uint32_t sbase = (uint32_t)__cvta_generic_to_shared(sbuf);

    // Stage one fp16 channel row (16KB) into ring buffer `buf`.
    auto stage = [&](int c, int buf) {
        const uint2* src = rfb + (size_t)c * NS;
        const uint32_t dst = sbase + (uint32_t)buf * ROW_BYTES;
        #pragma unroll
        for (int j = 0; j < NS / 2 / THREADS; ++j) {   // 2 iters of 16B chunks
            const int e = tid + j * THREADS;
            cp_async16(dst + e * 16, src + e * 2);
        }
    };

    // Prologue: stage channels 0..2 as groups g0..g2.
    stage(c0 + 0, 0); cp_async_commit();
    stage(c0 + 1, 1); cp_async_commit();
    stage(c0 + 2, 2); cp_async_commit();

    for (int k = 0; k < CPG; ++k) {
        // All warps done reading buffer (k+3)%4 before restaging; for k==0
        // this also orders the spr* smem writes.
        __syncthreads();

        if (k + 3 < CPG) stage(c0 + k + 3, (k + 3) & (NBUF - 1));
        cp_async_commit();          // exactly one group per iteration

        // Committed groups: g0..g_{k+3}. Leave 3 in flight -> g_k complete.
        cp_async_wait<3>();

        const uint2* cur = sbuf + (size_t)(k & (NBUF - 1)) * NS;
        const float prx = sprx[k];
        const float pry = spry[k];
        const float prz = sprz[k];

        #pragma unroll
        for (int j = 0; j < PXT; ++j) {
            const float dx = gx[j] - prx;
            const float dy = gy[j] - pry;
            const float dz = gz[j] - prz;
            float d2 = fmaf(dx, dx, fmaf(dy, dy, dz * dz));
            const float drx = d2 * rsqrtf(d2);   // d2==0 -> NaN -> clamped to 0

            float s = fmaf(scale, drx + gz[j], tbase);
            s = fminf(fmaxf(s, 0.0f), (float)(NS - 1));   // fmaxf eats NaN
            int i0 = min((int)s, NS - 2);
            const float w = s - (float)i0;
            const float omw = 1.0f - w;

            const uint2 v0 = cur[i0];
            const uint2 v1 = cur[i0 + 1];

            const float2 a0 = __half22float2(*reinterpret_cast<const __half2*>(&v0.x));
            const float2 a1 = __half22float2(*reinterpret_cast<const __half2*>(&v0.y));
            const float2 b0 = __half22float2(*reinterpret_cast<const __half2*>(&v1.x));
            const float2 b1 = __half22float2(*reinterpret_cast<const __half2*>(&v1.y));

            acc[j].x = fmaf(a0.x, omw, fmaf(b0.x, w, acc[j].x));
            acc[j].y = fmaf(a0.y, omw, fmaf(b0.y, w, acc[j].y));
            acc[j].z = fmaf(a1.x, omw, fmaf(b1.x, w, acc[j].z));
            acc[j].w = fmaf(a1.y, omw, fmaf(b1.y, w, acc[j].w));
        }
    }

    #pragma unroll
    for (int j = 0; j < PXT; ++j) {
        const int m = pm + tid + j * THREADS;
        red_add_v4(out + ((size_t)b * M + m) * 4, acc[j]);
    }
}

extern "C" void kernel_launch(void* const* d_in, const int* in_sizes, int n_in,
                              void* d_out, int out_size) {
    const float* rf = (const float*)d_in[0];  // [B, Nc, Ns, K]
    const float* g  = (const float*)d_in[1];  // [B, Nz, Nx, 3]
    const float* pr = (const float*)d_in[2];  // [B, Nc, 3]
    const float* p  = (const float*)d_in[3];  // [B, 4]
    float* out = (float*)d_out;               // [B, Nz, Nx, K]

    cudaFuncSetAttribute(das_fp16_kernel,
                         cudaFuncAttributeMaxDynamicSharedMemorySize, SMEM_BYTES);

    // Pass 1: rf -> fp16
    rf_to_fp16_kernel<<<(NSAMP + 255) / 256, 256>>>(
        reinterpret_cast<const float4*>(rf));

    // Zero output for atomic accumulation.
    cudaMemsetAsync(out, 0, (size_t)out_size * sizeof(float));

    // Pass 2: beamform
    dim3 grid(NB * TILES * NG);   // 2048 blocks
    das_fp16_kernel<<<grid, THREADS, SMEM_BYTES>>>(g, pr, p, out);
}

// round 6
// speedup vs baseline: 1.0795x; 1.0795x over previous
#include <cuda_runtime.h>
#include <cuda_fp16.h>
#include <cstdint>

// DAS beamforming: fp16-staged smem gather, 4-deep cp.async pipeline,
// packed f32x2 delay math (pixel pairs) + fp16 HFMA2 lerp.
// Pass 1: rf fp32 (8MB, L2-resident) -> fp16 __device__ buffer (4MB).
// Pass 2: block = (batch, 2048-pixel tile, 16-channel group); ring-buffer each
// channel's fp16 row (16KB) in smem via cp.async, gather y0/y1 as one LDS.64
// pair, lerp with HFMA2, accumulate fp32 via add.f32x2, combine partials with
// red.global.add.v4.f32.

namespace {
constexpr int NB = 2;
constexpr int NC = 128;
constexpr int NS = 2048;
constexpr int M  = 65536;
constexpr int THREADS = 512;
constexpr int PXT = 4;                    // pixels per thread (2 packed pairs)
constexpr int TILE_P = THREADS * PXT;     // 2048
constexpr int TILES = M / TILE_P;         // 32
constexpr int CPG = 16;                   // channels per block
constexpr int NG  = NC / CPG;             // 8
constexpr int ROW_BYTES = NS * 8;         // fp16 row: 2048 samples * 8B
constexpr int NBUF = 4;
constexpr int SMEM_BYTES = NBUF * ROW_BYTES;   // 64KB ring
constexpr int NSAMP = NB * NC * NS;
}

__device__ uint2 g_rf16[NSAMP];           // [B][Nc][Ns] x 4 halves = 4MB

// ---- packed f32x2 helpers (Blackwell; ptxas never emits these from C++) ----
typedef unsigned long long ull;
__device__ __forceinline__ ull f2x_pack(float lo, float hi) {
    ull r; asm("mov.b64 %0, {%1, %2};" : "=l"(r) : "f"(lo), "f"(hi)); return r;
}
__device__ __forceinline__ void f2x_unpack(ull v, float& lo, float& hi) {
    asm("mov.b64 {%0, %1}, %2;" : "=f"(lo), "=f"(hi) : "l"(v));
}
__device__ __forceinline__ ull f2x_add(ull a, ull b) {
    ull r; asm("add.rn.f32x2 %0, %1, %2;" : "=l"(r) : "l"(a), "l"(b)); return r;
}
__device__ __forceinline__ ull f2x_mul(ull a, ull b) {
    ull r; asm("mul.rn.f32x2 %0, %1, %2;" : "=l"(r) : "l"(a), "l"(b)); return r;
}
__device__ __forceinline__ ull f2x_fma(ull a, ull b, ull c) {
    ull r; asm("fma.rn.f32x2 %0, %1, %2, %3;" : "=l"(r) : "l"(a), "l"(b), "l"(c));
    return r;
}

__device__ __forceinline__ void cp_async16(uint32_t smem_addr, const void* gptr) {
    asm volatile("cp.async.cg.shared.global [%0], [%1], 16;\n"
                 :: "r"(smem_addr), "l"(gptr) : "memory");
}
__device__ __forceinline__ void cp_async_commit() {
    asm volatile("cp.async.commit_group;\n" ::: "memory");
}
template <int N>
__device__ __forceinline__ void cp_async_wait() {
    asm volatile("cp.async.wait_group %0;\n" :: "n"(N) : "memory");
}
__device__ __forceinline__ void red_add_v4(float* ptr, float x, float y, float z, float w) {
    asm volatile("red.global.add.v4.f32 [%0], {%1, %2, %3, %4};\n"
                 :: "l"(ptr), "f"(x), "f"(y), "f"(z), "f"(w) : "memory");
}

__global__ __launch_bounds__(256)
void rf_to_fp16_kernel(const float4* __restrict__ rf) {
    const int i = blockIdx.x * blockDim.x + threadIdx.x;
    if (i < NSAMP) {
        const float4 v = rf[i];
        const __half2 h0 = __float22half2_rn(make_float2(v.x, v.y));
        const __half2 h1 = __float22half2_rn(make_float2(v.z, v.w));
        uint2 u;
        u.x = *reinterpret_cast<const unsigned int*>(&h0);
        u.y = *reinterpret_cast<const unsigned int*>(&h1);
        g_rf16[i] = u;
    }
}

// Per-pixel: clamp delay, gather y0/y1, fp16 lerp, packed fp32 accumulate.
__device__ __forceinline__ void das_accum(float s, const uint2* __restrict__ cur,
                                          ull& acc_xy, ull& acc_zw) {
    s = fminf(fmaxf(s, 0.0f), (float)(NS - 1));   // fmaxf eats NaN (d2==0)
    int i0 = min((int)s, NS - 2);
    const float w = s - (float)i0;
    const __half2 wh = __float2half2_rn(w);

    const uint2 v0 = cur[i0];
    const uint2 v1 = cur[i0 + 1];
    const __half2 a0 = *reinterpret_cast<const __half2*>(&v0.x);
    const __half2 a1 = *reinterpret_cast<const __half2*>(&v0.y);
    const __half2 b0 = *reinterpret_cast<const __half2*>(&v1.x);
    const __half2 b1 = *reinterpret_cast<const __half2*>(&v1.y);

    const __half2 r0 = __hfma2(wh, __hsub2(b0, a0), a0);
    const __half2 r1 = __hfma2(wh, __hsub2(b1, a1), a1);

    const float2 f0 = __half22float2(r0);
    const float2 f1 = __half22float2(r1);
    acc_xy = f2x_add(acc_xy, f2x_pack(f0.x, f0.y));
    acc_zw = f2x_add(acc_zw, f2x_pack(f1.x, f1.y));
}

__global__ __launch_bounds__(THREADS, 3)
void das_fp16_kernel(const float* __restrict__ g,
                     const float* __restrict__ pr,
                     const float* __restrict__ p,
                     float* __restrict__ out) {
    extern __shared__ uint2 sbuf[];                 // [NBUF][NS]
    __shared__ float sprx[CPG], spry[CPG], sprz[CPG];   // NEGATED positions

    const int tid  = threadIdx.x;
    int idx = blockIdx.x;
    const int b    = idx / (TILES * NG);
    idx -= b * (TILES * NG);
    const int tile = idx / NG;
    const int grp  = idx - tile * NG;
    const int c0   = grp * CPG;
    const int pm   = tile * TILE_P;

    if (tid < CPG) {
        const float* prb = pr + ((size_t)b * NC + (c0 + tid)) * 3;
        sprx[tid] = -prb[0];
        spry[tid] = -prb[1];
        sprz[tid] = -prb[2];
    }

    const float c0s = p[b * 4 + 0];
    const float fs  = p[b * 4 + 1];
    const float t0  = p[b * 4 + 2];
    const float scale = fs / c0s;
    const float tbase = fs * t0 / c0s;
    const ull scale2 = f2x_pack(scale, scale);
    const ull tbase2 = f2x_pack(tbase, tbase);

    // Packed per-pixel-pair coordinates and fp32 accumulators.
    ull gx2[PXT / 2], gy2[PXT / 2], gz2[PXT / 2];
    ull acc_xy[PXT], acc_zw[PXT];
    #pragma unroll
    for (int j2 = 0; j2 < PXT / 2; ++j2) {
        const int ma = pm + tid + (2 * j2 + 0) * THREADS;
        const int mb = pm + tid + (2 * j2 + 1) * THREADS;
        const float* ga = g + ((size_t)b * M + ma) * 3;
        const float* gb = g + ((size_t)b * M + mb) * 3;
        gx2[j2] = f2x_pack(ga[0], gb[0]);
        gy2[j2] = f2x_pack(ga[1], gb[1]);
        gz2[j2] = f2x_pack(ga[2], gb[2]);
    }
    #pragma unroll
    for (int j = 0; j < PXT; ++j) { acc_xy[j] = 0ULL; acc_zw[j] = 0ULL; }

    const uint2* rfb = g_rf16 + (size_t)b * NC * NS;
    const uint32_t sbase = (uint32_t)__cvta_generic_to_shared(sbuf);

    auto stage = [&](int c, int buf) {
        const uint2* src = rfb + (size_t)c * NS;
        const uint32_t dst = sbase + (uint32_t)buf * ROW_BYTES;
        #pragma unroll
        for (int j = 0; j < NS / 2 / THREADS; ++j) {   // 2 iters of 16B chunks
            const int e = tid + j * THREADS;
            cp_async16(dst + e * 16, src + e * 2);
        }
    };

    stage(c0 + 0, 0); cp_async_commit();
    stage(c0 + 1, 1); cp_async_commit();
    stage(c0 + 2, 2); cp_async_commit();

    for (int k = 0; k < CPG; ++k) {
        __syncthreads();    // buffer (k+3)%4 free; k==0 also orders spr* writes

        if (k + 3 < CPG) stage(c0 + k + 3, (k + 3) & (NBUF - 1));
        cp_async_commit();          // exactly one group per iteration

        cp_async_wait<3>();         // groups g0..g_{k+3} committed -> g_k done

        const uint2* cur = sbuf + (size_t)(k & (NBUF - 1)) * NS;
        const ull nprx2 = f2x_pack(sprx[k], sprx[k]);
        const ull npry2 = f2x_pack(spry[k], spry[k]);
        const ull nprz2 = f2x_pack(sprz[k], sprz[k]);

        #pragma unroll
        for (int j2 = 0; j2 < PXT / 2; ++j2) {
            const ull dx2 = f2x_add(gx2[j2], nprx2);
            const ull dy2 = f2x_add(gy2[j2], npry2);
            const ull dz2 = f2x_add(gz2[j2], nprz2);
            ull d2 = f2x_mul(dz2, dz2);
            d2 = f2x_fma(dy2, dy2, d2);
            d2 = f2x_fma(dx2, dx2, d2);

            float d2a, d2b;
            f2x_unpack(d2, d2a, d2b);
            const ull r2 = f2x_pack(rsqrtf(d2a), rsqrtf(d2b));
            const ull drx2 = f2x_mul(d2, r2);          // sqrt(d2)
            const ull path2 = f2x_add(drx2, gz2[j2]);  // rx + tx(depth)
            const ull s2 = f2x_fma(scale2, path2, tbase2);

            float sa, sb;
            f2x_unpack(s2, sa, sb);
            das_accum(sa, cur, acc_xy[2 * j2 + 0], acc_zw[2 * j2 + 0]);
            das_accum(sb, cur, acc_xy[2 * j2 + 1], acc_zw[2 * j2 + 1]);
        }
    }

    #pragma unroll
    for (int j = 0; j < PXT; ++j) {
        const int m = pm + tid + j * THREADS;
        float x, y, z, w;
        f2x_unpack(acc_xy[j], x, y);
        f2x_unpack(acc_zw[j], z, w);
        red_add_v4(out + ((size_t)b * M + m) * 4, x, y, z, w);
    }
}

extern "C" void kernel_launch(void* const* d_in, const int* in_sizes, int n_in,
                              void* d_out, int out_size) {
    const float* rf = (const float*)d_in[0];  // [B, Nc, Ns, K]
    const float* g  = (const float*)d_in[1];  // [B, Nz, Nx, 3]
    const float* pr = (const float*)d_in[2];  // [B, Nc, 3]
    const float* p  = (const float*)d_in[3];  // [B, 4]
    float* out = (float*)d_out;               // [B, Nz, Nx, K]

    cudaFuncSetAttribute(das_fp16_kernel,
                         cudaFuncAttributeMaxDynamicSharedMemorySize, SMEM_BYTES);

    rf_to_fp16_kernel<<<(NSAMP + 255) / 256, 256>>>(
        reinterpret_cast<const float4*>(rf));

    cudaMemsetAsync(out, 0, (size_t)out_size * sizeof(float));

    dim3 grid(NB * TILES * NG);   // 512 blocks
    das_fp16_kernel<<<grid, THREADS, SMEM_BYTES>>>(g, pr, p, out);
}